// round 1
// baseline (speedup 1.0000x reference)
#include <cuda_runtime.h>
#include <math.h>

#define HEADS 4
#define RES 28
#define PSZ 14
#define PP 196
#define NB 32
#define NT 784
#define NC 768
#define CH 192
#define EPSF 1e-5f

// ---- persistent device scratch (no allocations allowed) ----
__device__ float g_An[HEADS * PP];   // [h][iy*14+jy]  column-stochastic over iy
__device__ float g_Bn[HEADS * PP];   // [h][ix*14+jx]  column-stochastic over ix
__device__ float g_mw[HEADS], g_vw[HEADS], g_omm[HEADS], g_omv[HEADS];
__device__ float g_xp[(size_t)NB * PP * NC];   // pooled xn, layout [b][patch][c]
__device__ float g_inv[NB * HEADS * NT];       // [b][h][t]
__device__ float g_mln[NB * NT];
__device__ float g_vln[NB * NT];

// ============================================================
// K0: sigmoids + separable softmax factor matrices (tiny)
// ============================================================
__global__ void k0_setup(const float* __restrict__ pw,
                         const float* __restrict__ mnw,
                         const float* __restrict__ vnw) {
    int tid = threadIdx.x;
    if (tid < 56) {                       // Bn: x-axis factor, task = (h, jx)
        int h = tid / 14, jx = tid % 14;
        float w0 = pw[h * 3 + 0], w2 = pw[h * 3 + 2];
        float s[14]; float mx = -1e30f;
        #pragma unroll
        for (int ix = 0; ix < 14; ix++) {
            float dx = (float)(jx - ix);
            float v = w0 * dx + w2 * dx * dx;
            s[ix] = v; mx = fmaxf(mx, v);
        }
        float sum = 0.f;
        #pragma unroll
        for (int ix = 0; ix < 14; ix++) { s[ix] = expf(s[ix] - mx); sum += s[ix]; }
        float r = 1.0f / sum;
        #pragma unroll
        for (int ix = 0; ix < 14; ix++) g_Bn[h * PP + ix * 14 + jx] = s[ix] * r;
    } else if (tid >= 64 && tid < 120) {  // An: y-axis factor, task = (h, jy)
        int t2 = tid - 64;
        int h = t2 / 14, jy = t2 % 14;
        float w1 = pw[h * 3 + 1], w2 = pw[h * 3 + 2];
        float s[14]; float mx = -1e30f;
        #pragma unroll
        for (int iy = 0; iy < 14; iy++) {
            float dy = (float)(jy - iy);
            float v = w1 * dy + w2 * dy * dy;
            s[iy] = v; mx = fmaxf(mx, v);
        }
        float sum = 0.f;
        #pragma unroll
        for (int iy = 0; iy < 14; iy++) { s[iy] = expf(s[iy] - mx); sum += s[iy]; }
        float r = 1.0f / sum;
        #pragma unroll
        for (int iy = 0; iy < 14; iy++) g_An[h * PP + iy * 14 + jy] = s[iy] * r;
    } else if (tid >= 120 && tid < 124) {
        int h = tid - 120;
        float m = 1.0f / (1.0f + expf(-mnw[h]));
        g_mw[h] = m; g_omm[h] = 1.0f - m;
    } else if (tid >= 124 && tid < 128) {
        int h = tid - 124;
        float v = 1.0f / (1.0f + expf(-vnw[h]));
        g_vw[h] = v; g_omv[h] = 1.0f - v;
    }
}

// ============================================================
// K1: per-token group stats + pooled xp.  block = (b, patch j)
// 256 threads, thread owns 3 consecutive channels (head-aligned: 192%3==0)
// ============================================================
__global__ void __launch_bounds__(256) k1_stats(const float* __restrict__ x) {
    int blk = blockIdx.x;
    int b = blk / PP, j = blk % PP;
    int py = j / 14, px = j % 14;
    int tid = threadIdx.x;
    int c0 = tid * 3;
    int head = tid >> 6;                 // 64 threads per head
    int baseT = (2 * py) * 28 + 2 * px;

    float xv[4][3];
    float s1[4], s2[4];
    #pragma unroll
    for (int tok = 0; tok < 4; tok++) {
        int t = baseT + (tok >> 1) * 28 + (tok & 1);
        const float* p = x + ((size_t)(b * NT + t)) * NC + c0;
        float a = p[0], bb = p[1], cc = p[2];
        xv[tok][0] = a; xv[tok][1] = bb; xv[tok][2] = cc;
        s1[tok] = a + bb + cc;
        s2[tok] = a * a + bb * bb + cc * cc;
    }
    // warp reduce (all 32 lanes of a warp share the same head)
    #pragma unroll
    for (int off = 16; off > 0; off >>= 1) {
        #pragma unroll
        for (int tok = 0; tok < 4; tok++) {
            s1[tok] += __shfl_down_sync(0xffffffffu, s1[tok], off);
            s2[tok] += __shfl_down_sync(0xffffffffu, s2[tok], off);
        }
    }
    __shared__ float rs1[8][4], rs2[8][4];
    __shared__ float sS1[4][4], sS2[4][4], sInv[4][4];  // [tok][head]
    int w = tid >> 5;
    if ((tid & 31) == 0) {
        #pragma unroll
        for (int tok = 0; tok < 4; tok++) { rs1[w][tok] = s1[tok]; rs2[w][tok] = s2[tok]; }
    }
    __syncthreads();
    if (tid < 16) {
        int tok = tid & 3, h = tid >> 2;
        float S1 = rs1[2 * h][tok] + rs1[2 * h + 1][tok];
        float S2 = rs2[2 * h][tok] + rs2[2 * h + 1][tok];
        float inv = rsqrtf(S2 * (1.0f / CH) + EPSF);
        sS1[tok][h] = S1; sS2[tok][h] = S2; sInv[tok][h] = inv;
        int t = baseT + (tok >> 1) * 28 + (tok & 1);
        g_inv[(b * HEADS + h) * NT + t] = inv;
    }
    __syncthreads();
    if (tid < 4) {
        int tok = tid;
        float sx = 0.f, sx2 = 0.f;
        #pragma unroll
        for (int h = 0; h < 4; h++) {
            float inv = sInv[tok][h];
            sx  += sS1[tok][h] * inv;
            sx2 += sS2[tok][h] * inv * inv;
        }
        float mean = sx * (1.0f / NC);
        float var = (sx2 - sx * mean) * (1.0f / (NC - 1));   // unbiased
        int t = baseT + (tok >> 1) * 28 + (tok & 1);
        g_mln[b * NT + t] = mean;
        g_vln[b * NT + t] = var;
    }
    float i0 = sInv[0][head], i1 = sInv[1][head], i2 = sInv[2][head], i3 = sInv[3][head];
    float* xpo = &g_xp[((size_t)(b * PP + j)) * NC + c0];
    #pragma unroll
    for (int k = 0; k < 3; k++) {
        xpo[k] = 0.25f * (xv[0][k] * i0 + xv[1][k] * i1 + xv[2][k] * i2 + xv[3][k] * i3);
    }
}

// ============================================================
// K2: separable pos-mix (two 14x14 contractions) + fused output epilogue
// block = (b, 32-channel tile). 224 threads = 7 warps; warp g owns rows g,g+7.
// ============================================================
#define K2T 224
#define SM_FLOATS (27832)

__global__ void __launch_bounds__(K2T, 2) k2_main(
        const float* __restrict__ x, const float* __restrict__ weight,
        const float* __restrict__ bias, float* __restrict__ out) {
    extern __shared__ float sm[];
    float* sXP  = sm;              // 196x32 pooled xn  (later reused for mean_r)
    float* sT1  = sm + 6272;       // 196x32 stage-1 mean
    float* sT2  = sm + 12544;      // 196x32 stage-1 mean-of-squares
    float* sV   = sm + 18816;      // 196x32 var_r (scaled)
    float* sMLN = sm + 25088;      // 784  mw*mean_ln
    float* sVLN = sm + 25872;      // 784  vw*var_ln
    float* sINV = sm + 26656;      // 784  inv for this head
    float* sA   = sm + 27440;      // 196
    float* sB   = sm + 27636;      // 196

    int b = blockIdx.x;
    int c0 = blockIdx.y * 32;
    int h = c0 / CH;
    int tid = threadIdx.x;

    const float* xpg = &g_xp[((size_t)b * PP) * NC + c0];
    for (int i = tid; i < 6272; i += K2T)
        sXP[i] = xpg[(size_t)(i >> 5) * NC + (i & 31)];
    float mwh = g_mw[h], vwh = g_vw[h];
    for (int i = tid; i < NT; i += K2T) {
        sMLN[i] = mwh * g_mln[b * NT + i];
        sVLN[i] = vwh * g_vln[b * NT + i];
        sINV[i] = g_inv[(b * HEADS + h) * NT + i];
    }
    for (int i = tid; i < PP; i += K2T) {
        sA[i] = g_An[h * PP + i];
        sB[i] = g_Bn[h * PP + i];
    }
    __syncthreads();

    int g = tid >> 5, cl = tid & 31;

    // ---- stage 1: contract over ix  (tmp[iy][jx] = sum_ix xp[iy][ix]*Bn[ix][jx])
    {
        float a1[2][14], a2[2][14];
        #pragma unroll
        for (int jx = 0; jx < 14; jx++) { a1[0][jx] = a1[1][jx] = a2[0][jx] = a2[1][jx] = 0.f; }
        #pragma unroll
        for (int ix = 0; ix < 14; ix++) {
            float v0 = sXP[(((g    ) * 14 + ix) << 5) + cl];
            float v1 = sXP[(((g + 7) * 14 + ix) << 5) + cl];
            float q0 = v0 * v0, q1 = v1 * v1;
            #pragma unroll
            for (int jx = 0; jx < 14; jx++) {
                float p = sB[ix * 14 + jx];
                a1[0][jx] = fmaf(v0, p, a1[0][jx]);
                a2[0][jx] = fmaf(q0, p, a2[0][jx]);
                a1[1][jx] = fmaf(v1, p, a1[1][jx]);
                a2[1][jx] = fmaf(q1, p, a2[1][jx]);
            }
        }
        #pragma unroll
        for (int jx = 0; jx < 14; jx++) {
            sT1[(((g    ) * 14 + jx) << 5) + cl] = a1[0][jx];
            sT2[(((g    ) * 14 + jx) << 5) + cl] = a2[0][jx];
            sT1[(((g + 7) * 14 + jx) << 5) + cl] = a1[1][jx];
            sT2[(((g + 7) * 14 + jx) << 5) + cl] = a2[1][jx];
        }
    }
    __syncthreads();

    // ---- stage 2: contract over iy; form scaled mean_r (into sXP) and var_r (sV)
    float omm = g_omm[h], omv = g_omv[h];
    {
        float m[2][14], m2[2][14];
        #pragma unroll
        for (int jx = 0; jx < 14; jx++) { m[0][jx] = m[1][jx] = m2[0][jx] = m2[1][jx] = 0.f; }
        #pragma unroll
        for (int iy = 0; iy < 14; iy++) {
            float p0 = sA[iy * 14 + g];
            float p1 = sA[iy * 14 + g + 7];
            #pragma unroll
            for (int jx = 0; jx < 14; jx++) {
                float t1v = sT1[((iy * 14 + jx) << 5) + cl];
                float t2v = sT2[((iy * 14 + jx) << 5) + cl];
                m [0][jx] = fmaf(p0, t1v, m [0][jx]);
                m2[0][jx] = fmaf(p0, t2v, m2[0][jx]);
                m [1][jx] = fmaf(p1, t1v, m [1][jx]);
                m2[1][jx] = fmaf(p1, t2v, m2[1][jx]);
            }
        }
        #pragma unroll
        for (int jx = 0; jx < 14; jx++) {
            float mm = m[0][jx];
            sXP[(((g    ) * 14 + jx) << 5) + cl] = omm * mm;
            sV [(((g    ) * 14 + jx) << 5) + cl] = omv * (m2[0][jx] - mm * mm);
            mm = m[1][jx];
            sXP[(((g + 7) * 14 + jx) << 5) + cl] = omm * mm;
            sV [(((g + 7) * 14 + jx) << 5) + cl] = omv * (m2[1][jx] - mm * mm);
        }
    }
    __syncthreads();

    // ---- fused epilogue: stream x -> out for this (b, c-tile)
    float wv = weight[c0 + cl], bv = bias[c0 + cl];
    const float* xr  = x   + (size_t)b * NT * NC + c0 + cl;
    float*       orr = out + (size_t)b * NT * NC + c0 + cl;
    #pragma unroll 2
    for (int i = tid; i < NT * 32; i += K2T) {
        int t = i >> 5;                       // cl is invariant (224 % 32 == 0)
        unsigned row = (unsigned)t / 28u;
        unsigned col = (unsigned)t - row * 28u;
        int j = (int)((row >> 1) * 14 + (col >> 1));
        float xval = __ldg(xr + (size_t)t * NC);
        float xn = xval * sINV[t];
        float mr = sXP[(j << 5) + cl] + sMLN[t];
        float vr = sV [(j << 5) + cl] + sVLN[t];
        orr[(size_t)t * NC] = (xn - mr) * rsqrtf(vr + EPSF) * wv + bv;
    }
}

// ============================================================
extern "C" void kernel_launch(void* const* d_in, const int* in_sizes, int n_in,
                              void* d_out, int out_size) {
    const float* x      = (const float*)d_in[0];
    const float* weight = (const float*)d_in[1];
    const float* bias   = (const float*)d_in[2];
    const float* mnw    = (const float*)d_in[3];
    const float* vnw    = (const float*)d_in[4];
    const float* pw     = (const float*)d_in[5];
    // d_in[6] = pos_b: cancels inside the softmax, unused.
    float* out = (float*)d_out;

    cudaFuncSetAttribute(k2_main, cudaFuncAttributeMaxDynamicSharedMemorySize,
                         SM_FLOATS * (int)sizeof(float));

    k0_setup<<<1, 128>>>(pw, mnw, vnw);
    k1_stats<<<NB * PP, 256>>>(x);
    k2_main<<<dim3(NB, NC / 32), K2T, SM_FLOATS * sizeof(float)>>>(x, weight, bias, out);
}

// round 2
// speedup vs baseline: 1.8587x; 1.8587x over previous
#include <cuda_runtime.h>
#include <math.h>

#define HEADS 4
#define RES 28
#define PSZ 14
#define PP 196
#define NB 32
#define NT 784
#define NC 768
#define CH 192
#define NCT 24            // channel tiles of 32
#define EPSF 1e-5f

// ---- persistent device scratch (no allocations allowed) ----
__device__ float g_xp[(size_t)NB * NCT * PP * 32];  // pooled xn, [b][ctile][patch][32]
__device__ float g_inv[NB * HEADS * NT];            // [b][h][t]
__device__ float g_mln[NB * NT];
__device__ float g_vln[NB * NT];

// ============================================================
// K1: per-token group stats + pooled xp.  block = (b, patch j)
// 256 threads, thread owns 3 consecutive channels (head-aligned: 192%3==0)
// ============================================================
__global__ void __launch_bounds__(256) k1_stats(const float* __restrict__ x) {
    int blk = blockIdx.x;
    int b = blk / PP, j = blk % PP;
    int py = j / 14, px = j % 14;
    int tid = threadIdx.x;
    int c0 = tid * 3;
    int head = tid >> 6;                 // 64 threads per head
    int baseT = (2 * py) * 28 + 2 * px;

    float xv[4][3];
    float s1[4], s2[4];
    #pragma unroll
    for (int tok = 0; tok < 4; tok++) {
        int t = baseT + (tok >> 1) * 28 + (tok & 1);
        const float* p = x + ((size_t)(b * NT + t)) * NC + c0;
        float a = p[0], bb = p[1], cc = p[2];
        xv[tok][0] = a; xv[tok][1] = bb; xv[tok][2] = cc;
        s1[tok] = a + bb + cc;
        s2[tok] = a * a + bb * bb + cc * cc;
    }
    #pragma unroll
    for (int off = 16; off > 0; off >>= 1) {
        #pragma unroll
        for (int tok = 0; tok < 4; tok++) {
            s1[tok] += __shfl_down_sync(0xffffffffu, s1[tok], off);
            s2[tok] += __shfl_down_sync(0xffffffffu, s2[tok], off);
        }
    }
    __shared__ float rs1[8][4], rs2[8][4];
    __shared__ float sS1[4][4], sS2[4][4], sInv[4][4];  // [tok][head]
    int w = tid >> 5;
    if ((tid & 31) == 0) {
        #pragma unroll
        for (int tok = 0; tok < 4; tok++) { rs1[w][tok] = s1[tok]; rs2[w][tok] = s2[tok]; }
    }
    __syncthreads();
    if (tid < 16) {
        int tok = tid & 3, h = tid >> 2;
        float S1 = rs1[2 * h][tok] + rs1[2 * h + 1][tok];
        float S2 = rs2[2 * h][tok] + rs2[2 * h + 1][tok];
        float inv = rsqrtf(S2 * (1.0f / CH) + EPSF);
        sS1[tok][h] = S1; sS2[tok][h] = S2; sInv[tok][h] = inv;
        int t = baseT + (tok >> 1) * 28 + (tok & 1);
        g_inv[(b * HEADS + h) * NT + t] = inv;
    }
    __syncthreads();
    if (tid < 4) {
        int tok = tid;
        float sx = 0.f, sx2 = 0.f;
        #pragma unroll
        for (int h = 0; h < 4; h++) {
            float inv = sInv[tok][h];
            sx  += sS1[tok][h] * inv;
            sx2 += sS2[tok][h] * inv * inv;
        }
        float mean = sx * (1.0f / NC);
        float var = (sx2 - sx * mean) * (1.0f / (NC - 1));
        int t = baseT + (tok >> 1) * 28 + (tok & 1);
        g_mln[b * NT + t] = mean;
        g_vln[b * NT + t] = var;
    }
    float i0 = sInv[0][head], i1 = sInv[1][head], i2 = sInv[2][head], i3 = sInv[3][head];
    #pragma unroll
    for (int k = 0; k < 3; k++) {
        int c = c0 + k;
        int ct = c >> 5, ln = c & 31;
        float v = 0.25f * (xv[0][k] * i0 + xv[1][k] * i1 + xv[2][k] * i2 + xv[3][k] * i3);
        g_xp[(((size_t)(b * NCT + ct)) * PP + j) * 32 + ln] = v;
    }
}

// ============================================================
// K2: separable pos-mix (two 14x14 contractions) + fused output epilogue
// block = (b, 32-channel tile). 224 threads = 7 warps; warp g owns rows g,g+7.
// ============================================================
#define K2T 224
#define SM_FLOATS (27832)

__global__ void __launch_bounds__(K2T, 2) k2_main(
        const float* __restrict__ x, const float* __restrict__ weight,
        const float* __restrict__ bias, const float* __restrict__ mnw,
        const float* __restrict__ vnw, const float* __restrict__ pw,
        float* __restrict__ out) {
    extern __shared__ float sm[];
    float* sXP  = sm;              // 196x32 pooled xn  (later reused for mean_r)
    float* sT1  = sm + 6272;       // 196x32 stage-1 mean
    float* sT2  = sm + 12544;      // 196x32 stage-1 mean-of-squares
    float* sV   = sm + 18816;      // 196x32 var_r (scaled)
    float* sMLN = sm + 25088;      // 784  mw*mean_ln
    float* sVLN = sm + 25872;      // 784  vw*var_ln
    float* sINV = sm + 26656;      // 784  inv for this head
    float* sA   = sm + 27440;      // 196  y-factor [iy*14+jy]
    float* sB   = sm + 27636;      // 196  x-factor [ix*14+jx]

    int b = blockIdx.x;
    int ctile = blockIdx.y;
    int c0 = ctile * 32;
    int h = ctile / 6;             // 6 tiles per head (192/32)
    int tid = threadIdx.x;

    // per-thread sigmoid gates (cheap, avoids a setup kernel)
    float mwh = 1.0f / (1.0f + expf(-mnw[h]));
    float vwh = 1.0f / (1.0f + expf(-vnw[h]));
    float omm = 1.0f - mwh, omv = 1.0f - vwh;

    // in-block separable softmax factors (pos_b cancels in softmax)
    if (tid < 14) {                       // Bn: x-axis factor, column jx
        int jx = tid;
        float w0 = pw[h * 3 + 0], w2 = pw[h * 3 + 2];
        float s[14]; float mx = -1e30f;
        #pragma unroll
        for (int ix = 0; ix < 14; ix++) {
            float dx = (float)(jx - ix);
            float v = w0 * dx + w2 * dx * dx;
            s[ix] = v; mx = fmaxf(mx, v);
        }
        float sum = 0.f;
        #pragma unroll
        for (int ix = 0; ix < 14; ix++) { s[ix] = expf(s[ix] - mx); sum += s[ix]; }
        float r = 1.0f / sum;
        #pragma unroll
        for (int ix = 0; ix < 14; ix++) sB[ix * 14 + jx] = s[ix] * r;
    } else if (tid >= 32 && tid < 46) {   // An: y-axis factor, column jy
        int jy = tid - 32;
        float w1 = pw[h * 3 + 1], w2 = pw[h * 3 + 2];
        float s[14]; float mx = -1e30f;
        #pragma unroll
        for (int iy = 0; iy < 14; iy++) {
            float dy = (float)(jy - iy);
            float v = w1 * dy + w2 * dy * dy;
            s[iy] = v; mx = fmaxf(mx, v);
        }
        float sum = 0.f;
        #pragma unroll
        for (int iy = 0; iy < 14; iy++) { s[iy] = expf(s[iy] - mx); sum += s[iy]; }
        float r = 1.0f / sum;
        #pragma unroll
        for (int iy = 0; iy < 14; iy++) sA[iy * 14 + jy] = s[iy] * r;
    }

    // vectorized smem prologue
    {
        const float4* xpg = (const float4*)&g_xp[(((size_t)(b * NCT + ctile)) * PP) * 32];
        float4* dXP = (float4*)sXP;
        for (int i = tid; i < 6272 / 4; i += K2T) dXP[i] = xpg[i];

        const float4* mg = (const float4*)(g_mln + b * NT);
        const float4* vg = (const float4*)(g_vln + b * NT);
        const float4* ig = (const float4*)(g_inv + (b * HEADS + h) * NT);
        float4* dM = (float4*)sMLN; float4* dV = (float4*)sVLN; float4* dI = (float4*)sINV;
        for (int i = tid; i < NT / 4; i += K2T) {
            float4 m = mg[i], v = vg[i];
            m.x *= mwh; m.y *= mwh; m.z *= mwh; m.w *= mwh;
            v.x *= vwh; v.y *= vwh; v.z *= vwh; v.w *= vwh;
            dM[i] = m; dV[i] = v; dI[i] = ig[i];
        }
    }
    __syncthreads();

    int g = tid >> 5, cl = tid & 31;

    // ---- stage 1: contract over ix  (tmp[iy][jx] = sum_ix xp[iy][ix]*Bn[ix][jx])
    {
        float a1[2][14], a2[2][14];
        #pragma unroll
        for (int jx = 0; jx < 14; jx++) { a1[0][jx] = a1[1][jx] = a2[0][jx] = a2[1][jx] = 0.f; }
        #pragma unroll
        for (int ix = 0; ix < 14; ix++) {
            float v0 = sXP[(((g    ) * 14 + ix) << 5) + cl];
            float v1 = sXP[(((g + 7) * 14 + ix) << 5) + cl];
            float q0 = v0 * v0, q1 = v1 * v1;
            #pragma unroll
            for (int jx = 0; jx < 14; jx++) {
                float p = sB[ix * 14 + jx];
                a1[0][jx] = fmaf(v0, p, a1[0][jx]);
                a2[0][jx] = fmaf(q0, p, a2[0][jx]);
                a1[1][jx] = fmaf(v1, p, a1[1][jx]);
                a2[1][jx] = fmaf(q1, p, a2[1][jx]);
            }
        }
        #pragma unroll
        for (int jx = 0; jx < 14; jx++) {
            sT1[(((g    ) * 14 + jx) << 5) + cl] = a1[0][jx];
            sT2[(((g    ) * 14 + jx) << 5) + cl] = a2[0][jx];
            sT1[(((g + 7) * 14 + jx) << 5) + cl] = a1[1][jx];
            sT2[(((g + 7) * 14 + jx) << 5) + cl] = a2[1][jx];
        }
    }
    __syncthreads();

    // ---- stage 2: contract over iy; form scaled mean_r (into sXP) and var_r (sV)
    {
        float m[2][14], m2[2][14];
        #pragma unroll
        for (int jx = 0; jx < 14; jx++) { m[0][jx] = m[1][jx] = m2[0][jx] = m2[1][jx] = 0.f; }
        #pragma unroll
        for (int iy = 0; iy < 14; iy++) {
            float p0 = sA[iy * 14 + g];
            float p1 = sA[iy * 14 + g + 7];
            #pragma unroll
            for (int jx = 0; jx < 14; jx++) {
                float t1v = sT1[((iy * 14 + jx) << 5) + cl];
                float t2v = sT2[((iy * 14 + jx) << 5) + cl];
                m [0][jx] = fmaf(p0, t1v, m [0][jx]);
                m2[0][jx] = fmaf(p0, t2v, m2[0][jx]);
                m [1][jx] = fmaf(p1, t1v, m [1][jx]);
                m2[1][jx] = fmaf(p1, t2v, m2[1][jx]);
            }
        }
        #pragma unroll
        for (int jx = 0; jx < 14; jx++) {
            float mm = m[0][jx];
            sXP[(((g    ) * 14 + jx) << 5) + cl] = omm * mm;
            sV [(((g    ) * 14 + jx) << 5) + cl] = omv * (m2[0][jx] - mm * mm);
            mm = m[1][jx];
            sXP[(((g + 7) * 14 + jx) << 5) + cl] = omm * mm;
            sV [(((g + 7) * 14 + jx) << 5) + cl] = omv * (m2[1][jx] - mm * mm);
        }
    }
    __syncthreads();

    // ---- fused epilogue: stream x -> out (float4, 4-deep batched loads)
    int q = tid & 7;                     // float4 slot within 32-ch tile
    int tb = tid >> 3;                   // token slot 0..27
    float4 wv = ((const float4*)(weight + c0))[q];
    float4 bv = ((const float4*)(bias   + c0))[q];
    const float4* xr  = (const float4*)(x   + (size_t)b * NT * NC + c0);
    float4*       orr = (float4*)      (out + (size_t)b * NT * NC + c0);
    const int rs = NC / 4;               // row stride in float4

    #pragma unroll 1
    for (int it = 0; it < 7; ++it) {
        float4 xv[4];
        int tt[4];
        #pragma unroll
        for (int u = 0; u < 4; u++) {
            int t = tb + (it * 4 + u) * 28;
            tt[u] = t;
            xv[u] = __ldg(&xr[(size_t)t * rs + q]);
        }
        #pragma unroll
        for (int u = 0; u < 4; u++) {
            int t = tt[u];
            unsigned row = (unsigned)t / 28u;
            unsigned col = (unsigned)t - row * 28u;
            int j = (int)((row >> 1) * 14 + (col >> 1));
            float inv = sINV[t], ml = sMLN[t], vl = sVLN[t];
            float4 mr = ((const float4*)(sXP + (j << 5)))[q];
            float4 vr = ((const float4*)(sV  + (j << 5)))[q];
            float4 o;
            o.x = (xv[u].x * inv - (mr.x + ml)) * rsqrtf(vr.x + vl + EPSF) * wv.x + bv.x;
            o.y = (xv[u].y * inv - (mr.y + ml)) * rsqrtf(vr.y + vl + EPSF) * wv.y + bv.y;
            o.z = (xv[u].z * inv - (mr.z + ml)) * rsqrtf(vr.z + vl + EPSF) * wv.z + bv.z;
            o.w = (xv[u].w * inv - (mr.w + ml)) * rsqrtf(vr.w + vl + EPSF) * wv.w + bv.w;
            orr[(size_t)t * rs + q] = o;
        }
    }
}

// ============================================================
extern "C" void kernel_launch(void* const* d_in, const int* in_sizes, int n_in,
                              void* d_out, int out_size) {
    const float* x      = (const float*)d_in[0];
    const float* weight = (const float*)d_in[1];
    const float* bias   = (const float*)d_in[2];
    const float* mnw    = (const float*)d_in[3];
    const float* vnw    = (const float*)d_in[4];
    const float* pw     = (const float*)d_in[5];
    // d_in[6] = pos_b: cancels inside the softmax, unused.
    float* out = (float*)d_out;

    cudaFuncSetAttribute(k2_main, cudaFuncAttributeMaxDynamicSharedMemorySize,
                         SM_FLOATS * (int)sizeof(float));

    k1_stats<<<NB * PP, 256>>>(x);
    k2_main<<<dim3(NB, NCT), K2T, SM_FLOATS * sizeof(float)>>>(
        x, weight, bias, mnw, vnw, pw, out);
}

// round 3
// speedup vs baseline: 2.1553x; 1.1596x over previous
#include <cuda_runtime.h>
#include <math.h>

#define HEADS 4
#define RES 28
#define PSZ 14
#define PP 196
#define NB 32
#define NT 784
#define NC 768
#define CH 192
#define NCT 24            // channel tiles of 32
#define EPSF 1e-5f

// ---- persistent device scratch (no allocations allowed) ----
__device__ float g_xp[(size_t)NB * NCT * PP * 32];  // pooled xn, [b][ctile][patch][32]
__device__ float g_inv[NB * HEADS * NT];            // [b][h][t]
__device__ float g_mln[NB * NT];
__device__ float g_vln[NB * NT];

// ============================================================
// K1: per-token group stats + pooled xp.  block = (b, patch j)
// 192 threads; thread owns 4 consecutive channels (float4).
// 48 threads per head = 3 head-uniform 16-lane segments.
// ============================================================
__global__ void __launch_bounds__(192) k1_stats(const float* __restrict__ x) {
    int blk = blockIdx.x;
    int b = blk / PP, j = blk % PP;
    int py = j / 14, px = j % 14;
    int tid = threadIdx.x;
    int head = tid / 48;
    int c0 = head * CH + (tid % 48) * 4;
    int baseT = (2 * py) * 28 + 2 * px;

    float4 xv[4];
    float s1[4], s2[4];
    #pragma unroll
    for (int tok = 0; tok < 4; tok++) {
        int t = baseT + (tok >> 1) * 28 + (tok & 1);
        float4 v = __ldg((const float4*)(x + ((size_t)(b * NT + t)) * NC + c0));
        xv[tok] = v;
        s1[tok] = v.x + v.y + v.z + v.w;
        s2[tok] = v.x * v.x + v.y * v.y + v.z * v.z + v.w * v.w;
    }
    // width-16 segment reduce (each 16-lane segment is head-uniform: 48 = 3*16)
    #pragma unroll
    for (int off = 8; off > 0; off >>= 1) {
        #pragma unroll
        for (int tok = 0; tok < 4; tok++) {
            s1[tok] += __shfl_down_sync(0xffffffffu, s1[tok], off, 16);
            s2[tok] += __shfl_down_sync(0xffffffffu, s2[tok], off, 16);
        }
    }
    __shared__ float rs1[12][4], rs2[12][4];        // [segment][tok]
    __shared__ float sS1[4][4], sS2[4][4], sInv[4][4];  // [tok][head]
    int seg = tid >> 4;
    if ((tid & 15) == 0) {
        #pragma unroll
        for (int tok = 0; tok < 4; tok++) { rs1[seg][tok] = s1[tok]; rs2[seg][tok] = s2[tok]; }
    }
    __syncthreads();
    if (tid < 16) {
        int tok = tid & 3, h = tid >> 2;
        float S1 = rs1[3 * h][tok] + rs1[3 * h + 1][tok] + rs1[3 * h + 2][tok];
        float S2 = rs2[3 * h][tok] + rs2[3 * h + 1][tok] + rs2[3 * h + 2][tok];
        float inv = rsqrtf(S2 * (1.0f / CH) + EPSF);
        sS1[tok][h] = S1; sS2[tok][h] = S2; sInv[tok][h] = inv;
        int t = baseT + (tok >> 1) * 28 + (tok & 1);
        g_inv[(b * HEADS + h) * NT + t] = inv;
    }
    __syncthreads();
    if (tid < 4) {
        int tok = tid;
        float sx = 0.f, sx2 = 0.f;
        #pragma unroll
        for (int h = 0; h < 4; h++) {
            float inv = sInv[tok][h];
            sx  += sS1[tok][h] * inv;
            sx2 += sS2[tok][h] * inv * inv;
        }
        float mean = sx * (1.0f / NC);
        float var = (sx2 - sx * mean) * (1.0f / (NC - 1));
        int t = baseT + (tok >> 1) * 28 + (tok & 1);
        g_mln[b * NT + t] = mean;
        g_vln[b * NT + t] = var;
    }
    float i0 = sInv[0][head], i1 = sInv[1][head], i2 = sInv[2][head], i3 = sInv[3][head];
    float4 o;
    o.x = 0.25f * (xv[0].x * i0 + xv[1].x * i1 + xv[2].x * i2 + xv[3].x * i3);
    o.y = 0.25f * (xv[0].y * i0 + xv[1].y * i1 + xv[2].y * i2 + xv[3].y * i3);
    o.z = 0.25f * (xv[0].z * i0 + xv[1].z * i1 + xv[2].z * i2 + xv[3].z * i3);
    o.w = 0.25f * (xv[0].w * i0 + xv[1].w * i1 + xv[2].w * i2 + xv[3].w * i3);
    int ct = c0 >> 5, ln = c0 & 31;
    *(float4*)&g_xp[(((size_t)(b * NCT + ct)) * PP + j) * 32 + ln] = o;
}

// ============================================================
// K2: separable pos-mix + fused output epilogue.
// block = (b, 32-channel tile). 224 threads = 7 warps; warp g owns rows g,g+7.
// smem ~60KB, launch_bounds(224,3) -> 3 blocks/SM, 21 warps.
// ============================================================
#define K2T 224
#define SM_FLOATS (12544 + 784 * 3 + 392)   // sT1,sT2 + token arrays + sA,sB

__global__ void __launch_bounds__(K2T, 3) k2_main(
        const float* __restrict__ x, const float* __restrict__ weight,
        const float* __restrict__ bias, const float* __restrict__ mnw,
        const float* __restrict__ vnw, const float* __restrict__ pw,
        float* __restrict__ out) {
    extern __shared__ float sm[];
    float* sT1  = sm;              // 196x32 stage-1 mean     (later: scaled mean_r)
    float* sT2  = sm + 6272;       // 196x32 stage-1 sq-mean  (later: scaled var_r)
    float* sMLN = sm + 12544;      // 784  mw*mean_ln
    float* sVLN = sm + 13328;      // 784  vw*var_ln
    float* sINV = sm + 14112;      // 784  inv for this head
    float* sA   = sm + 14896;      // 196  y-factor [iy*14+jy]
    float* sB   = sm + 15092;      // 196  x-factor [ix*14+jx]

    int b = blockIdx.x;
    int ctile = blockIdx.y;
    int c0 = ctile * 32;
    int h = ctile / 6;             // 6 tiles per head (192/32)
    int tid = threadIdx.x;

    float mwh = 1.0f / (1.0f + expf(-mnw[h]));
    float vwh = 1.0f / (1.0f + expf(-vnw[h]));
    float omm = 1.0f - mwh, omv = 1.0f - vwh;

    // in-block separable softmax factors (pos_b cancels in softmax)
    if (tid < 14) {                       // Bn: x-axis factor, column jx
        int jx = tid;
        float w0 = pw[h * 3 + 0], w2 = pw[h * 3 + 2];
        float s[14]; float mx = -1e30f;
        #pragma unroll
        for (int ix = 0; ix < 14; ix++) {
            float dx = (float)(jx - ix);
            float v = w0 * dx + w2 * dx * dx;
            s[ix] = v; mx = fmaxf(mx, v);
        }
        float sum = 0.f;
        #pragma unroll
        for (int ix = 0; ix < 14; ix++) { s[ix] = expf(s[ix] - mx); sum += s[ix]; }
        float r = 1.0f / sum;
        #pragma unroll
        for (int ix = 0; ix < 14; ix++) sB[ix * 14 + jx] = s[ix] * r;
    } else if (tid >= 32 && tid < 46) {   // An: y-axis factor, column jy
        int jy = tid - 32;
        float w1 = pw[h * 3 + 1], w2 = pw[h * 3 + 2];
        float s[14]; float mx = -1e30f;
        #pragma unroll
        for (int iy = 0; iy < 14; iy++) {
            float dy = (float)(jy - iy);
            float v = w1 * dy + w2 * dy * dy;
            s[iy] = v; mx = fmaxf(mx, v);
        }
        float sum = 0.f;
        #pragma unroll
        for (int iy = 0; iy < 14; iy++) { s[iy] = expf(s[iy] - mx); sum += s[iy]; }
        float r = 1.0f / sum;
        #pragma unroll
        for (int iy = 0; iy < 14; iy++) sA[iy * 14 + jy] = s[iy] * r;
    }

    // token-stat prologue (vectorized)
    {
        const float4* mg = (const float4*)(g_mln + b * NT);
        const float4* vg = (const float4*)(g_vln + b * NT);
        const float4* ig = (const float4*)(g_inv + (b * HEADS + h) * NT);
        float4* dM = (float4*)sMLN; float4* dV = (float4*)sVLN; float4* dI = (float4*)sINV;
        for (int i = tid; i < NT / 4; i += K2T) {
            float4 m = mg[i], v = vg[i];
            m.x *= mwh; m.y *= mwh; m.z *= mwh; m.w *= mwh;
            v.x *= vwh; v.y *= vwh; v.z *= vwh; v.w *= vwh;
            dM[i] = m; dV[i] = v; dI[i] = ig[i];
        }
    }
    __syncthreads();

    int g = tid >> 5, cl = tid & 31;
    const float* xpg = &g_xp[(((size_t)(b * NCT + ctile)) * PP) * 32];

    // ---- stage 1: contract over ix  (tmp[iy][jx] = sum_ix xp[iy][ix]*Bn[ix][jx])
    // warp g owns pooled rows iy = g and g+7; xp read direct from global (coalesced 128B rows)
    {
        float a1[2][14], a2[2][14];
        #pragma unroll
        for (int jx = 0; jx < 14; jx++) { a1[0][jx] = a1[1][jx] = a2[0][jx] = a2[1][jx] = 0.f; }
        #pragma unroll
        for (int ix = 0; ix < 14; ix++) {
            float v0 = __ldg(xpg + (((g    ) * 14 + ix) << 5) + cl);
            float v1 = __ldg(xpg + (((g + 7) * 14 + ix) << 5) + cl);
            float q0 = v0 * v0, q1 = v1 * v1;
            #pragma unroll
            for (int jx = 0; jx < 14; jx++) {
                float p = sB[ix * 14 + jx];
                a1[0][jx] = fmaf(v0, p, a1[0][jx]);
                a2[0][jx] = fmaf(q0, p, a2[0][jx]);
                a1[1][jx] = fmaf(v1, p, a1[1][jx]);
                a2[1][jx] = fmaf(q1, p, a2[1][jx]);
            }
        }
        #pragma unroll
        for (int jx = 0; jx < 14; jx++) {
            sT1[(((g    ) * 14 + jx) << 5) + cl] = a1[0][jx];
            sT2[(((g    ) * 14 + jx) << 5) + cl] = a2[0][jx];
            sT1[(((g + 7) * 14 + jx) << 5) + cl] = a1[1][jx];
            sT2[(((g + 7) * 14 + jx) << 5) + cl] = a2[1][jx];
        }
    }
    __syncthreads();

    // ---- stage 2: contract over iy; accumulate in regs, write back in place
    {
        float m[2][14], m2[2][14];
        #pragma unroll
        for (int jx = 0; jx < 14; jx++) { m[0][jx] = m[1][jx] = m2[0][jx] = m2[1][jx] = 0.f; }
        #pragma unroll
        for (int iy = 0; iy < 14; iy++) {
            float p0 = sA[iy * 14 + g];
            float p1 = sA[iy * 14 + g + 7];
            #pragma unroll
            for (int jx = 0; jx < 14; jx++) {
                float t1v = sT1[((iy * 14 + jx) << 5) + cl];
                float t2v = sT2[((iy * 14 + jx) << 5) + cl];
                m [0][jx] = fmaf(p0, t1v, m [0][jx]);
                m2[0][jx] = fmaf(p0, t2v, m2[0][jx]);
                m [1][jx] = fmaf(p1, t1v, m [1][jx]);
                m2[1][jx] = fmaf(p1, t2v, m2[1][jx]);
            }
        }
        __syncthreads();   // all reads of sT1/sT2 done before overwrite
        #pragma unroll
        for (int jx = 0; jx < 14; jx++) {
            float mm = m[0][jx];
            sT1[(((g    ) * 14 + jx) << 5) + cl] = omm * mm;
            sT2[(((g    ) * 14 + jx) << 5) + cl] = omv * (m2[0][jx] - mm * mm);
            mm = m[1][jx];
            sT1[(((g + 7) * 14 + jx) << 5) + cl] = omm * mm;
            sT2[(((g + 7) * 14 + jx) << 5) + cl] = omv * (m2[1][jx] - mm * mm);
        }
    }
    __syncthreads();

    // ---- fused epilogue: stream x -> out (float4, 4-deep batched loads)
    int q = tid & 7;                     // float4 slot within 32-ch tile
    int tb = tid >> 3;                   // token slot 0..27
    float4 wv = ((const float4*)(weight + c0))[q];
    float4 bv = ((const float4*)(bias   + c0))[q];
    const float4* xr  = (const float4*)(x   + (size_t)b * NT * NC + c0);
    float4*       orr = (float4*)      (out + (size_t)b * NT * NC + c0);
    const int rs = NC / 4;               // row stride in float4

    #pragma unroll 1
    for (int it = 0; it < 7; ++it) {
        float4 xv[4];
        int tt[4];
        #pragma unroll
        for (int u = 0; u < 4; u++) {
            int t = tb + (it * 4 + u) * 28;
            tt[u] = t;
            xv[u] = __ldg(&xr[(size_t)t * rs + q]);
        }
        #pragma unroll
        for (int u = 0; u < 4; u++) {
            int t = tt[u];
            unsigned row = (unsigned)t / 28u;
            unsigned col = (unsigned)t - row * 28u;
            int j = (int)((row >> 1) * 14 + (col >> 1));
            float inv = sINV[t], ml = sMLN[t], vl = sVLN[t];
            float4 mr = ((const float4*)(sT1 + (j << 5)))[q];
            float4 vr = ((const float4*)(sT2 + (j << 5)))[q];
            float4 o;
            o.x = (xv[u].x * inv - (mr.x + ml)) * rsqrtf(vr.x + vl + EPSF) * wv.x + bv.x;
            o.y = (xv[u].y * inv - (mr.y + ml)) * rsqrtf(vr.y + vl + EPSF) * wv.y + bv.y;
            o.z = (xv[u].z * inv - (mr.z + ml)) * rsqrtf(vr.z + vl + EPSF) * wv.z + bv.z;
            o.w = (xv[u].w * inv - (mr.w + ml)) * rsqrtf(vr.w + vl + EPSF) * wv.w + bv.w;
            orr[(size_t)t * rs + q] = o;
        }
    }
}

// ============================================================
extern "C" void kernel_launch(void* const* d_in, const int* in_sizes, int n_in,
                              void* d_out, int out_size) {
    const float* x      = (const float*)d_in[0];
    const float* weight = (const float*)d_in[1];
    const float* bias   = (const float*)d_in[2];
    const float* mnw    = (const float*)d_in[3];
    const float* vnw    = (const float*)d_in[4];
    const float* pw     = (const float*)d_in[5];
    // d_in[6] = pos_b: cancels inside the softmax, unused.
    float* out = (float*)d_out;

    cudaFuncSetAttribute(k2_main, cudaFuncAttributeMaxDynamicSharedMemorySize,
                         SM_FLOATS * (int)sizeof(float));

    k1_stats<<<NB * PP, 192>>>(x);
    k2_main<<<dim3(NB, NCT), K2T, SM_FLOATS * sizeof(float)>>>(
        x, weight, bias, mnw, vnw, pw, out);
}